// round 10
// baseline (speedup 1.0000x reference)
#include <cuda_runtime.h>
#include <cstdint>
#include <cstddef>

// ---------------- problem constants ----------------
#define D_MODEL   1024
#define D_PROJ    256
#define MTILE     128                  // rows per CTA
#define NCHUNKS   32                   // K chunks of 32 fp32 (128B per row)
#define EPS1      1e-5f

// smem map (bytes):
//   [0, 4096)      suv: u[256] v[256] g2[256] b2[256]
//   [4096, 6144)   s1p[512]
//   [6144, 8192)   s2p[512]
//   [8192, 9216)   ca[128] cb[128]
//   [12288, ...)   3 stages: A 16KB + B 32KB each
//   epilogue reuses stage0: rowacc[128][4][2] (4KB), mu2[128], rs2[128]
#define SMEM_STAGE_OFF 12288
#define A_BYTES   16384                // 128 rows x 128B
#define B_BYTES   32768                // 256 rows x 128B
#define STAGE_BYTES 49152u
#define SMEM_BYTES (SMEM_STAGE_OFF + 3 * 49152)   // 159744

// ---------------- device scratch ----------------
// g_Wp layout: [p][kc*32 + s], slot s = 16h+4c+j holds k_local = 16h+c+4j.
__device__ float g_Wp[D_PROJ * D_MODEL];
__device__ float g_u[D_PROJ];
__device__ float g_v[D_PROJ];

// ---------------- helpers ----------------
static __device__ __forceinline__ uint32_t smem_u32(const void* p) {
    uint32_t a;
    asm("{ .reg .u64 t; cvta.to.shared.u64 t, %1; cvt.u32.u64 %0, t; }" : "=r"(a) : "l"(p));
    return a;
}

// conflict-free group swizzle: sigma(r) = ((r&1)<<2) | ((r>>1)&3)
static __device__ __forceinline__ uint32_t sig(int r) {
    return (((uint32_t)r & 1u) << 2) | (((uint32_t)r >> 1) & 3u);
}

#define CP_COMMIT() asm volatile("cp.async.commit_group;" ::: "memory")
#define CP_WAIT1()  asm volatile("cp.async.wait_group 1;" ::: "memory")

static __device__ __forceinline__ uint32_t f2tf32(float f) {
    uint32_t u;
    asm("cvt.rna.tf32.f32 %0, %1;" : "=r"(u) : "f"(f));
    return u;
}

// raw fp32 bits fed to tf32 MMA (truncation round on A; B pre-rounded rna)
#define MMA_TF32(d, a0, a1, a2, a3, b0, b1)                                   \
    asm volatile("mma.sync.aligned.m16n8k8.row.col.f32.tf32.tf32.f32 "        \
        "{%0,%1,%2,%3}, {%4,%5,%6,%7}, {%8,%9}, {%0,%1,%2,%3};"               \
        : "+f"((d)[0]), "+f"((d)[1]), "+f"((d)[2]), "+f"((d)[3])              \
        : "r"(a0), "r"(a1), "r"(a2), "r"(a3), "r"(b0), "r"(b1))

// LDS with the offset folded into the instruction (IMM must be a literal)
#define LDSAI(v, base, IMM)                                                   \
    asm volatile("ld.shared.v4.b32 {%0,%1,%2,%3}, [%4+%5];"                   \
        : "=r"((v).x), "=r"((v).y), "=r"((v).z), "=r"((v).w)                  \
        : "r"(base), "n"(IMM))

#define LDS128F(v, addr)                                                      \
    asm volatile("ld.shared.v4.f32 {%0,%1,%2,%3}, [%4];"                      \
        : "=f"((v).x), "=f"((v).y), "=f"((v).z), "=f"((v).w) : "r"(addr))

// cp.async with both offsets as instruction immediates
#define CPA4I(ADST, APTR, I)                                                  \
    asm volatile("cp.async.ca.shared.global [%0+%1], [%2+%3], 4;"             \
        :: "r"(ADST), "n"((I) * 2048), "l"(APTR), "n"((I) * 65536))

#define CPB16I(BDST, BPTR, I)                                                 \
    asm volatile("cp.async.cg.shared.global [%0+%1], [%2+%3], 16;"            \
        :: "r"(BDST), "n"((I) * 8192), "l"(BPTR), "n"((I) * 262144))

// ---------------- prep: W' = g1.*W (tf32-rna), permuted layout; u, v ----------------
__global__ void __launch_bounds__(256) prep_kernel(
    const float* __restrict__ W, const float* __restrict__ g1,
    const float* __restrict__ b1, const float* __restrict__ bias)
{
    __shared__ float ru[8], rv[8];
    int p = blockIdx.x, t = threadIdx.x;
    const float* wrow = W + (size_t)p * D_MODEL;
    float u = 0.f, v = 0.f;
#pragma unroll
    for (int i = 0; i < 4; ++i) {
        int d = t + i * 256;
        float w  = wrow[d];
        float gw = g1[d] * w;
        u += gw;
        v += b1[d] * w;
        int kc = d >> 5, kk = d & 31;
        int h = kk >> 4, c = kk & 3, j = (kk >> 2) & 3;
        int s = (h << 4) | (c << 2) | j;
        g_Wp[(size_t)p * D_MODEL + kc * 32 + s] = __uint_as_float(f2tf32(gw));
    }
#pragma unroll
    for (int o = 16; o > 0; o >>= 1) {
        u += __shfl_xor_sync(0xFFFFFFFFu, u, o);
        v += __shfl_xor_sync(0xFFFFFFFFu, v, o);
    }
    if ((t & 31) == 0) { ru[t >> 5] = u; rv[t >> 5] = v; }
    __syncthreads();
    if (t == 0) {
        float uu = 0.f, vv = 0.f;
#pragma unroll
        for (int i = 0; i < 8; ++i) { uu += ru[i]; vv += rv[i]; }
        g_u[p] = uu;
        g_v[p] = vv + bias[p];
    }
}

// ---------------- main fused kernel: 512 threads, warp tile 32x64 ----------------
__global__ void __launch_bounds__(512, 1) fused_kernel(
    const float* __restrict__ x,
    const float* __restrict__ g2v, const float* __restrict__ b2v,
    float* __restrict__ out)
{
    extern __shared__ char smem[];
    const uint32_t sb = smem_u32(smem);
    const int tid  = threadIdx.x;
    const int lane = tid & 31;
    const int wid  = tid >> 5;          // 0..15
    const int wm   = wid >> 2;          // 0..3  (m group: rows wm*32..wm*32+31)
    const int wn   = wid & 3;           // 0..3  (n slice: cols wn*64..wn*64+63)
    const int qt   = lane & 3;
    const int qr   = lane >> 2;

    float* suv = (float*)smem;          // u, v, g2, b2
    if (tid < 256) {
        suv[tid]       = g_u[tid];
        suv[256 + tid] = g_v[tid];
        suv[512 + tid] = g2v[tid];
        suv[768 + tid] = b2v[tid];
    }

    const size_t row0 = (size_t)blockIdx.x * MTILE;

    // ---- A loader: thread covers rows r = 16i + rb (i<8), element kk = tid&31 ----
    const int akk = tid & 31;
    const int rb  = tid >> 5;           // 0..15
    const int ahh = akk >> 4, acc_ = akk & 3, ajj = (akk >> 2) & 3;
    const uint32_t aGlog = (uint32_t)(4 * ahh + acc_);
    const uint32_t a_dst = sb + SMEM_STAGE_OFF + (uint32_t)rb * 128
                         + (((aGlog ^ sig(rb)) << 4)) + (uint32_t)ajj * 4;
    const char* a_cp = (const char*)x + (row0 + (size_t)rb) * 4096 + (size_t)akk * 4;

    // ---- B loader: thread covers rows p = 64i + tp (i<4), group bq = tid&7 ----
    const int tp = tid >> 3, bq = tid & 7;          // tp 0..63
    const uint32_t b_dst = sb + SMEM_STAGE_OFF + A_BYTES + (uint32_t)tp * 128
                         + ((((uint32_t)bq ^ sig(tp)) << 4));
    const char* b_cp = (const char*)g_Wp + (size_t)tp * 4096 + (size_t)bq * 16;

    // ---- fragment bases (h enters via XOR 64) ----
    const uint32_t qoff = (((uint32_t)qt ^ sig(qr)) << 4);
    const uint32_t aRow = sb + SMEM_STAGE_OFF + (uint32_t)(wm * 32 + qr) * 128;
    const uint32_t bRow = sb + SMEM_STAGE_OFF + A_BYTES + (uint32_t)(wn * 64 + qr) * 128;
    const uint32_t aF0 = aRow + qoff;
    const uint32_t aF1 = aRow + (qoff ^ 64u);
    const uint32_t bF0 = bRow + qoff;
    const uint32_t bF1 = bRow + (qoff ^ 64u);

    // ---- LN1 stat consts: thread -> row srow, quarter sg (2 float4 groups) ----
    const int srow = tid & 127, sg = tid >> 7;      // sg 0..3
    const uint32_t sBase = sb + SMEM_STAGE_OFF + (uint32_t)srow * 128;
    const uint32_t ssig = sig(srow);
    const uint32_t sA0 = sBase + (((uint32_t)(sg * 2)     ^ ssig) << 4);
    const uint32_t sA1 = sBase + (((uint32_t)(sg * 2 + 1) ^ ssig) << 4);

    float acc[2][8][4];
#pragma unroll
    for (int a = 0; a < 2; ++a)
#pragma unroll
        for (int b = 0; b < 8; ++b)
#pragma unroll
            for (int c = 0; c < 4; ++c) acc[a][b][c] = 0.f;

    float s1 = 0.f, s2 = 0.f;

// load one chunk from current a_cp/b_cp into stage at smem offset (runtime reg)
#define LOADC(ADSTS, BDSTS)                                                    \
    do {                                                                       \
        CPA4I((ADSTS), a_cp, 0); CPA4I((ADSTS), a_cp, 1);                      \
        CPA4I((ADSTS), a_cp, 2); CPA4I((ADSTS), a_cp, 3);                      \
        CPA4I((ADSTS), a_cp, 4); CPA4I((ADSTS), a_cp, 5);                      \
        CPA4I((ADSTS), a_cp, 6); CPA4I((ADSTS), a_cp, 7);                      \
        CPB16I((BDSTS), b_cp, 0); CPB16I((BDSTS), b_cp, 1);                    \
        CPB16I((BDSTS), b_cp, 2); CPB16I((BDSTS), b_cp, 3);                    \
        a_cp += 128; b_cp += 128;                                              \
    } while (0)

#define STATS(SOFF)                                                            \
    do {                                                                       \
        float4 v0, v1;                                                         \
        LDS128F(v0, sA0 + (SOFF));                                             \
        LDS128F(v1, sA1 + (SOFF));                                             \
        s1 += ((v0.x + v0.y) + (v0.z + v0.w))                                  \
            + ((v1.x + v1.y) + (v1.z + v1.w));                                 \
        s2 += ((v0.x * v0.x + v0.y * v0.y) + (v0.z * v0.z + v0.w * v0.w))      \
            + ((v1.x * v1.x + v1.y * v1.y) + (v1.z * v1.z + v1.w * v1.w));     \
    } while (0)

#define MMASTEP(NT)                                                            \
    do {                                                                       \
        uint4 bb;                                                              \
        LDSAI(bb, _bf, (NT) * 1024);                                           \
        MMA_TF32(acc[0][NT], a0lo.x, a0hi.x, a0lo.y, a0hi.y, bb.x, bb.y);      \
        MMA_TF32(acc[1][NT], a1lo.x, a1hi.x, a1lo.y, a1hi.y, bb.x, bb.y);      \
        MMA_TF32(acc[0][NT], a0lo.z, a0hi.z, a0lo.w, a0hi.w, bb.z, bb.w);      \
        MMA_TF32(acc[1][NT], a1lo.z, a1hi.z, a1lo.w, a1hi.w, bb.z, bb.w);      \
    } while (0)

#define COMPUTE_H(AFB, BFB, SOFF)                                              \
    do {                                                                       \
        const uint32_t _af = (AFB) + (SOFF);                                   \
        const uint32_t _bf = (BFB) + (SOFF);                                   \
        uint4 a0lo, a0hi, a1lo, a1hi;                                          \
        LDSAI(a0lo, _af, 0);                                                   \
        LDSAI(a0hi, _af, 1024);                                                \
        LDSAI(a1lo, _af, 2048);                                                \
        LDSAI(a1hi, _af, 3072);                                                \
        MMASTEP(0); MMASTEP(1); MMASTEP(2); MMASTEP(3);                        \
        MMASTEP(4); MMASTEP(5); MMASTEP(6); MMASTEP(7);                        \
    } while (0)

#define COMPUTE(SOFF)                                                          \
    do {                                                                       \
        COMPUTE_H(aF0, bF0, (SOFF));                                           \
        COMPUTE_H(aF1, bF1, (SOFF));                                           \
    } while (0)

    // ---------------- mainloop: 3-stage pipeline, wait_group 1 ----------------
    {
        const uint32_t ad0 = a_dst, bd0 = b_dst;
        LOADC(ad0, bd0); CP_COMMIT();
        const uint32_t ad1 = a_dst + STAGE_BYTES, bd1 = b_dst + STAGE_BYTES;
        LOADC(ad1, bd1); CP_COMMIT();
    }

    uint32_t soff = 0;
#pragma unroll 1
    for (int kc = 0; kc < NCHUNKS; ++kc) {
        CP_WAIT1();                     // chunk kc resident
        __syncthreads();                // stage (kc+2)%3 free for overwrite
        if (kc + 2 < NCHUNKS) {
            uint32_t so2 = (soff == 0) ? 2u * STAGE_BYTES : soff - STAGE_BYTES;
            LOADC(a_dst + so2, b_dst + so2);
        }
        CP_COMMIT();
        STATS(soff);
        COMPUTE(soff);
        soff = (soff == 2u * STAGE_BYTES) ? 0u : soff + STAGE_BYTES;
    }

    // ---------------- LN1 finalize ----------------
    float* s1p = (float*)(smem + 4096);             // [512]
    float* s2p = (float*)(smem + 6144);             // [512]
    float* ca  = (float*)(smem + 8192);             // [128]
    float* cb  = ca + 128;                          // [128]
    float* rowacc = (float*)(smem + SMEM_STAGE_OFF);        // [128][4][2]
    float* mu2a = (float*)(smem + SMEM_STAGE_OFF + 4096);
    float* rs2a = mu2a + 128;

    s1p[tid] = s1; s2p[tid] = s2;
    __syncthreads();

    if (tid < 128) {
        float a = (s1p[tid] + s1p[tid + 128]) + (s1p[tid + 256] + s1p[tid + 384]);
        float b = (s2p[tid] + s2p[tid + 128]) + (s2p[tid + 256] + s2p[tid + 384]);
        float mu  = a * (1.0f / (float)D_MODEL);
        float var = fmaf(-mu, mu, b * (1.0f / (float)D_MODEL));
        float rs  = rsqrtf(var + EPS1);
        ca[tid] = rs;
        cb[tid] = -mu * rs;
    }
    rowacc[tid] = 0.f; rowacc[tid + 512] = 0.f;
    __syncthreads();

    // ---------------- h = ca*acc + cb*u + v; LN2 partial sums ----------------
#pragma unroll
    for (int mt = 0; mt < 2; ++mt) {
#pragma unroll
        for (int b = 0; b < 2; ++b) {
            int rr = wm * 32 + mt * 16 + qr + 8 * b;
            float cav = ca[rr], cbv = cb[rr];
            float t1 = 0.f, t2 = 0.f;
#pragma unroll
            for (int nt = 0; nt < 8; ++nt) {
                int p0 = wn * 64 + nt * 8 + 2 * qt;
                float h0 = fmaf(cav, acc[mt][nt][2 * b],     fmaf(cbv, suv[p0],     suv[256 + p0]));
                float h1 = fmaf(cav, acc[mt][nt][2 * b + 1], fmaf(cbv, suv[p0 + 1], suv[256 + p0 + 1]));
                acc[mt][nt][2 * b]     = h0;
                acc[mt][nt][2 * b + 1] = h1;
                t1 += h0 + h1;
                t2 += h0 * h0 + h1 * h1;
            }
            t1 += __shfl_xor_sync(0xFFFFFFFFu, t1, 1);
            t2 += __shfl_xor_sync(0xFFFFFFFFu, t2, 1);
            t1 += __shfl_xor_sync(0xFFFFFFFFu, t1, 2);
            t2 += __shfl_xor_sync(0xFFFFFFFFu, t2, 2);
            if (qt == 0) {
                rowacc[(rr * 4 + wn) * 2]     = t1;
                rowacc[(rr * 4 + wn) * 2 + 1] = t2;
            }
        }
    }
    __syncthreads();

    if (tid < 128) {
        float t1 = 0.f, t2 = 0.f;
#pragma unroll
        for (int w = 0; w < 4; ++w) {
            t1 += rowacc[(tid * 4 + w) * 2];
            t2 += rowacc[(tid * 4 + w) * 2 + 1];
        }
        float mu  = t1 * (1.0f / (float)D_PROJ);
        float var = fmaf(-mu, mu, t2 * (1.0f / (float)D_PROJ));
        mu2a[tid] = mu;
        rs2a[tid] = rsqrtf(var + EPS1);
    }
    __syncthreads();

    // ---------------- normalize + store ----------------
    float* outp = out + row0 * D_PROJ;
#pragma unroll
    for (int mt = 0; mt < 2; ++mt) {
#pragma unroll
        for (int b = 0; b < 2; ++b) {
            int rr = wm * 32 + mt * 16 + qr + 8 * b;
            float mu = mu2a[rr], rs = rs2a[rr];
#pragma unroll
            for (int nt = 0; nt < 8; ++nt) {
                int p0 = wn * 64 + nt * 8 + 2 * qt;
                float o0 = fmaf((acc[mt][nt][2 * b]     - mu) * rs, suv[512 + p0],     suv[768 + p0]);
                float o1 = fmaf((acc[mt][nt][2 * b + 1] - mu) * rs, suv[512 + p0 + 1], suv[768 + p0 + 1]);
                float2 o = make_float2(o0, o1);
                *(float2*)(outp + (size_t)rr * D_PROJ + p0) = o;
            }
        }
    }
#undef LOADC
#undef STATS
#undef MMASTEP
#undef COMPUTE_H
#undef COMPUTE
}

// ---------------- launch ----------------
extern "C" void kernel_launch(void* const* d_in, const int* in_sizes, int n_in,
                              void* d_out, int out_size)
{
    const float* x    = (const float*)d_in[0];
    const float* g1   = (const float*)d_in[1];
    const float* b1   = (const float*)d_in[2];
    const float* W    = (const float*)d_in[3];
    const float* bias = (const float*)d_in[4];
    const float* g2   = (const float*)d_in[5];
    const float* b2   = (const float*)d_in[6];
    float* out = (float*)d_out;

    int n_tok = in_sizes[0] / D_MODEL;          // 65536
    int grid  = n_tok / MTILE;                  // 512

    prep_kernel<<<D_PROJ, 256>>>(W, g1, b1, bias);

    cudaFuncSetAttribute(fused_kernel, cudaFuncAttributeMaxDynamicSharedMemorySize, SMEM_BYTES);
    fused_kernel<<<grid, 512, SMEM_BYTES>>>(x, g2, b2, out);
}

// round 11
// speedup vs baseline: 1.1431x; 1.1431x over previous
#include <cuda_runtime.h>
#include <cstdint>
#include <cstddef>

// ---------------- problem constants ----------------
#define D_MODEL   1024
#define D_PROJ    256
#define MTILE     128                  // rows per CTA
#define NCHUNKS   32                   // K chunks of 32 fp32 (128B per row)
#define EPS1      1e-5f

// smem map (bytes):
//   [0, 4096)      suv: u[256] v[256] g2[256] b2[256]
//   [4096, 6144)   s1p[256] s2p[256]
//   [6144, 7168)   ca[128] cb[128]
//   [8192, ...)    3 stages: A 16KB + B 32KB each
//   epilogue reuses stage0: rowacc[128][4][2] (4KB), mu2[128], rs2[128]
#define SMEM_STAGE_OFF 8192
#define A_BYTES   16384                // 128 rows x 128B
#define B_BYTES   32768                // 256 rows x 128B
#define STAGE_BYTES 49152u
#define SMEM_BYTES (SMEM_STAGE_OFF + 3 * 49152)   // 155648

// ---------------- device scratch ----------------
// g_Wp layout: [p][kc*32 + s], slot s = 16h+4c+j holds k_local = 16h+c+4j.
__device__ float g_Wp[D_PROJ * D_MODEL];
__device__ float g_u[D_PROJ];
__device__ float g_v[D_PROJ];

// ---------------- helpers ----------------
static __device__ __forceinline__ uint32_t smem_u32(const void* p) {
    uint32_t a;
    asm("{ .reg .u64 t; cvta.to.shared.u64 t, %1; cvt.u32.u64 %0, t; }" : "=r"(a) : "l"(p));
    return a;
}

// conflict-free group swizzle: sigma(r) = ((r&1)<<2) | ((r>>1)&3)
static __device__ __forceinline__ uint32_t sig(int r) {
    return (((uint32_t)r & 1u) << 2) | (((uint32_t)r >> 1) & 3u);
}

#define CP_COMMIT() asm volatile("cp.async.commit_group;" ::: "memory")
#define CP_WAIT1()  asm volatile("cp.async.wait_group 1;" ::: "memory")

static __device__ __forceinline__ uint32_t f2tf32(float f) {
    uint32_t u;
    asm("cvt.rna.tf32.f32 %0, %1;" : "=r"(u) : "f"(f));
    return u;
}

// raw fp32 bits fed to tf32 MMA (truncation round on A; B pre-rounded rna)
#define MMA_TF32(d, a0, a1, a2, a3, b0, b1)                                   \
    asm volatile("mma.sync.aligned.m16n8k8.row.col.f32.tf32.tf32.f32 "        \
        "{%0,%1,%2,%3}, {%4,%5,%6,%7}, {%8,%9}, {%0,%1,%2,%3};"               \
        : "+f"((d)[0]), "+f"((d)[1]), "+f"((d)[2]), "+f"((d)[3])              \
        : "r"(a0), "r"(a1), "r"(a2), "r"(a3), "r"(b0), "r"(b1))

#define LDS128F(v, addr)                                                      \
    asm volatile("ld.shared.v4.f32 {%0,%1,%2,%3}, [%4];"                      \
        : "=f"((v).x), "=f"((v).y), "=f"((v).z), "=f"((v).w) : "r"(addr))

#define LDS128U(v, addr)                                                      \
    asm volatile("ld.shared.v4.b32 {%0,%1,%2,%3}, [%4];"                      \
        : "=r"((v).x), "=r"((v).y), "=r"((v).z), "=r"((v).w) : "r"(addr))

// ---------------- prep: W' = g1.*W (tf32-rna), permuted layout; u, v ----------------
__global__ void __launch_bounds__(256) prep_kernel(
    const float* __restrict__ W, const float* __restrict__ g1,
    const float* __restrict__ b1, const float* __restrict__ bias)
{
    __shared__ float ru[8], rv[8];
    int p = blockIdx.x, t = threadIdx.x;
    const float* wrow = W + (size_t)p * D_MODEL;
    float u = 0.f, v = 0.f;
#pragma unroll
    for (int i = 0; i < 4; ++i) {
        int d = t + i * 256;
        float w  = wrow[d];
        float gw = g1[d] * w;
        u += gw;
        v += b1[d] * w;
        int kc = d >> 5, kk = d & 31;
        int h = kk >> 4, c = kk & 3, j = (kk >> 2) & 3;
        int s = (h << 4) | (c << 2) | j;
        g_Wp[(size_t)p * D_MODEL + kc * 32 + s] = __uint_as_float(f2tf32(gw));
    }
#pragma unroll
    for (int o = 16; o > 0; o >>= 1) {
        u += __shfl_xor_sync(0xFFFFFFFFu, u, o);
        v += __shfl_xor_sync(0xFFFFFFFFu, v, o);
    }
    if ((t & 31) == 0) { ru[t >> 5] = u; rv[t >> 5] = v; }
    __syncthreads();
    if (t == 0) {
        float uu = 0.f, vv = 0.f;
#pragma unroll
        for (int i = 0; i < 8; ++i) { uu += ru[i]; vv += rv[i]; }
        g_u[p] = uu;
        g_v[p] = vv + bias[p];
    }
}

// ---------------- main fused kernel ----------------
__global__ void __launch_bounds__(256, 1) fused_kernel(
    const float* __restrict__ x,
    const float* __restrict__ g2v, const float* __restrict__ b2v,
    float* __restrict__ out)
{
    extern __shared__ char smem[];
    const uint32_t sb = smem_u32(smem);
    const int tid  = threadIdx.x;
    const int lane = tid & 31;
    const int wid  = tid >> 5;
    const int wm   = wid >> 2;          // 0..1
    const int wn   = wid & 3;           // 0..3
    const int qt   = lane & 3;
    const int qr   = lane >> 2;

    float* suv = (float*)smem;          // u, v, g2, b2
    suv[tid]       = g_u[tid];
    suv[256 + tid] = g_v[tid];
    suv[512 + tid] = g2v[tid];
    suv[768 + tid] = b2v[tid];

    const size_t row0 = (size_t)blockIdx.x * MTILE;

    // ---- A loader consts: thread covers rows r = 8i + wid, element kk = tid&31 ----
    const int akk = tid & 31;
    const int ahh = akk >> 4, acc_ = akk & 3, ajj = (akk >> 2) & 3;
    const uint32_t aGlog = (uint32_t)(4 * ahh + acc_);
    const uint32_t a_dst = sb + SMEM_STAGE_OFF + (uint32_t)wid * 128
                         + (((aGlog ^ sig(wid)) << 4)) + (uint32_t)ajj * 4;
    const char* a_src = (const char*)x + (row0 + (size_t)wid) * 4096 + (size_t)akk * 4;

    // ---- B loader consts: thread covers rows p = 32i + tp, group bq = tid&7 ----
    const int tp = tid >> 3, bq = tid & 7;
    const uint32_t b_dst = sb + SMEM_STAGE_OFF + A_BYTES + (uint32_t)tp * 128
                         + ((((uint32_t)bq ^ sig(tp)) << 4));
    const char* b_src = (const char*)g_Wp + (size_t)tp * 4096 + (size_t)bq * 16;

    // ---- fragment bases, both halves precomputed (h enters via XOR 64) ----
    const uint32_t qoff = (((uint32_t)qt ^ sig(qr)) << 4);
    const uint32_t aRow = sb + SMEM_STAGE_OFF + (uint32_t)(wm * 64 + qr) * 128;
    const uint32_t bRow = sb + SMEM_STAGE_OFF + A_BYTES + (uint32_t)(wn * 64 + qr) * 128;
    const uint32_t aF0 = aRow + qoff;
    const uint32_t aF1 = aRow + (qoff ^ 64u);
    const uint32_t bF0 = bRow + qoff;
    const uint32_t bF1 = bRow + (qoff ^ 64u);

    // ---- LN1 stat consts ----
    const int srow = tid & 127, shh = tid >> 7;
    const uint32_t sBase = sb + SMEM_STAGE_OFF + (uint32_t)srow * 128;
    const uint32_t ssig = sig(srow);
    uint32_t sOff[4];
#pragma unroll
    for (int i = 0; i < 4; ++i)
        sOff[i] = (((uint32_t)(shh * 4 + i) ^ ssig) << 4);

    float acc[4][8][4];
#pragma unroll
    for (int a = 0; a < 4; ++a)
#pragma unroll
        for (int b = 0; b < 8; ++b)
#pragma unroll
            for (int c = 0; c < 4; ++c) acc[a][b][c] = 0.f;

    float s1 = 0.f, s2 = 0.f;

#define LOADC(KC, SOFF)                                                        \
    do {                                                                       \
        const char* _a = a_src + (size_t)(KC) * 128;                           \
        _Pragma("unroll")                                                      \
        for (int i = 0; i < 16; ++i)                                           \
            asm volatile("cp.async.ca.shared.global [%0], [%1], 4;"            \
                :: "r"(a_dst + (SOFF) + (uint32_t)i * 1024),                   \
                   "l"(_a + (size_t)i * 32768));                               \
        const char* _b = b_src + (size_t)(KC) * 128;                           \
        _Pragma("unroll")                                                      \
        for (int i = 0; i < 8; ++i)                                            \
            asm volatile("cp.async.cg.shared.global [%0], [%1], 16;"           \
                :: "r"(b_dst + (SOFF) + (uint32_t)i * 4096),                   \
                   "l"(_b + (size_t)i * 131072));                              \
    } while (0)

#define STATS(SOFF)                                                            \
    do {                                                                       \
        _Pragma("unroll")                                                      \
        for (int i = 0; i < 4; ++i) {                                          \
            float4 vv;                                                         \
            LDS128F(vv, sBase + (SOFF) + sOff[i]);                             \
            s1 += (vv.x + vv.y) + (vv.z + vv.w);                               \
            s2 += (vv.x * vv.x + vv.y * vv.y) + (vv.z * vv.z + vv.w * vv.w);   \
        }                                                                      \
    } while (0)

// 16 MMAs consuming one resident A-fragment pair against 8 B fragments
#define MMABLK(MT, BLO, BHI, BB)                                               \
    do {                                                                       \
        _Pragma("unroll")                                                      \
        for (int nt = 0; nt < 8; ++nt)                                         \
            MMA_TF32(acc[MT][nt], (BLO).x, (BHI).x, (BLO).y, (BHI).y,          \
                     (BB)[nt].x, (BB)[nt].y);                                  \
        _Pragma("unroll")                                                      \
        for (int nt = 0; nt < 8; ++nt)                                         \
            MMA_TF32(acc[MT][nt], (BLO).z, (BHI).z, (BLO).w, (BHI).w,          \
                     (BB)[nt].z, (BB)[nt].w);                                  \
    } while (0)

#define LOADA(LO, HI, ADDR)                                                    \
    do { LDS128U(LO, (ADDR)); LDS128U(HI, (ADDR) + 1024); } while (0)

// software-pipelined chunk: all B hoisted, A ping-pong prefetch
#define COMPUTE(SOFF)                                                          \
    do {                                                                       \
        uint4 bb0[8], bb1[8];                                                  \
        _Pragma("unroll")                                                      \
        for (int nt = 0; nt < 8; ++nt)                                         \
            LDS128U(bb0[nt], bF0 + (SOFF) + (uint32_t)nt * 1024);              \
        _Pragma("unroll")                                                      \
        for (int nt = 0; nt < 8; ++nt)                                         \
            LDS128U(bb1[nt], bF1 + (SOFF) + (uint32_t)nt * 1024);              \
        uint4 plo, phi, qlo, qhi;                                              \
        LOADA(plo, phi, aF0 + (SOFF));             /* h0 mt0 */                \
        LOADA(qlo, qhi, aF0 + (SOFF) + 2048);      /* h0 mt1 */                \
        MMABLK(0, plo, phi, bb0);                                              \
        LOADA(plo, phi, aF0 + (SOFF) + 4096);      /* h0 mt2 */                \
        MMABLK(1, qlo, qhi, bb0);                                              \
        LOADA(qlo, qhi, aF0 + (SOFF) + 6144);      /* h0 mt3 */                \
        MMABLK(2, plo, phi, bb0);                                              \
        LOADA(plo, phi, aF1 + (SOFF));             /* h1 mt0 */                \
        MMABLK(3, qlo, qhi, bb0);                                              \
        LOADA(qlo, qhi, aF1 + (SOFF) + 2048);      /* h1 mt1 */                \
        MMABLK(0, plo, phi, bb1);                                              \
        LOADA(plo, phi, aF1 + (SOFF) + 4096);      /* h1 mt2 */                \
        MMABLK(1, qlo, qhi, bb1);                                              \
        LOADA(qlo, qhi, aF1 + (SOFF) + 6144);      /* h1 mt3 */                \
        MMABLK(2, plo, phi, bb1);                                              \
        MMABLK(3, qlo, qhi, bb1);                                              \
    } while (0)

    // ---------------- mainloop: 3-stage pipeline, wait_group 1 ----------------
    LOADC(0, 0u); CP_COMMIT();
    LOADC(1, (uint32_t)STAGE_BYTES); CP_COMMIT();

    uint32_t soff = 0;
#pragma unroll 1
    for (int kc = 0; kc < NCHUNKS; ++kc) {
        CP_WAIT1();                     // chunk kc resident
        __syncthreads();                // stage (kc+2)%3 free for overwrite
        if (kc + 2 < NCHUNKS) {
            uint32_t so2 = (soff == 0) ? 2u * STAGE_BYTES : soff - STAGE_BYTES;
            LOADC(kc + 2, so2);
        }
        CP_COMMIT();
        COMPUTE(soff);
        STATS(soff);                    // after MMAs: latency overlaps next wait
        soff = (soff == 2u * STAGE_BYTES) ? 0u : soff + STAGE_BYTES;
    }

    // ---------------- LN1 finalize ----------------
    float* s1p = (float*)(smem + 4096);
    float* s2p = s1p + 256;
    float* ca = (float*)(smem + 6144);
    float* cb = ca + 128;
    float* rowacc = (float*)(smem + SMEM_STAGE_OFF);        // [128][4][2]
    float* mu2a = (float*)(smem + SMEM_STAGE_OFF + 4096);
    float* rs2a = mu2a + 128;

    s1p[tid] = s1; s2p[tid] = s2;
    __syncthreads();

    if (tid < 128) {
        float a = s1p[tid] + s1p[tid + 128];
        float b = s2p[tid] + s2p[tid + 128];
        float mu  = a * (1.0f / (float)D_MODEL);
        float var = fmaf(-mu, mu, b * (1.0f / (float)D_MODEL));
        float rs  = rsqrtf(var + EPS1);
        ca[tid] = rs;
        cb[tid] = -mu * rs;
    }
    rowacc[tid] = 0.f; rowacc[tid + 256] = 0.f;
    rowacc[tid + 512] = 0.f; rowacc[tid + 768] = 0.f;
    __syncthreads();

    // ---------------- h = ca*acc + cb*u + v; LN2 partial sums ----------------
#pragma unroll
    for (int mt = 0; mt < 4; ++mt) {
#pragma unroll
        for (int b = 0; b < 2; ++b) {
            int rr = wm * 64 + mt * 16 + qr + 8 * b;
            float cav = ca[rr], cbv = cb[rr];
            float t1 = 0.f, t2 = 0.f;
#pragma unroll
            for (int nt = 0; nt < 8; ++nt) {
                int p0 = wn * 64 + nt * 8 + 2 * qt;
                float h0 = fmaf(cav, acc[mt][nt][2 * b],     fmaf(cbv, suv[p0],     suv[256 + p0]));
                float h1 = fmaf(cav, acc[mt][nt][2 * b + 1], fmaf(cbv, suv[p0 + 1], suv[256 + p0 + 1]));
                acc[mt][nt][2 * b]     = h0;
                acc[mt][nt][2 * b + 1] = h1;
                t1 += h0 + h1;
                t2 += h0 * h0 + h1 * h1;
            }
            t1 += __shfl_xor_sync(0xFFFFFFFFu, t1, 1);
            t2 += __shfl_xor_sync(0xFFFFFFFFu, t2, 1);
            t1 += __shfl_xor_sync(0xFFFFFFFFu, t1, 2);
            t2 += __shfl_xor_sync(0xFFFFFFFFu, t2, 2);
            if (qt == 0) {
                rowacc[(rr * 4 + wn) * 2]     = t1;
                rowacc[(rr * 4 + wn) * 2 + 1] = t2;
            }
        }
    }
    __syncthreads();

    if (tid < 128) {
        float t1 = 0.f, t2 = 0.f;
#pragma unroll
        for (int w = 0; w < 4; ++w) {
            t1 += rowacc[(tid * 4 + w) * 2];
            t2 += rowacc[(tid * 4 + w) * 2 + 1];
        }
        float mu  = t1 * (1.0f / (float)D_PROJ);
        float var = fmaf(-mu, mu, t2 * (1.0f / (float)D_PROJ));
        mu2a[tid] = mu;
        rs2a[tid] = rsqrtf(var + EPS1);
    }
    __syncthreads();

    // ---------------- normalize + store ----------------
    float* outp = out + row0 * D_PROJ;
#pragma unroll
    for (int mt = 0; mt < 4; ++mt) {
#pragma unroll
        for (int b = 0; b < 2; ++b) {
            int rr = wm * 64 + mt * 16 + qr + 8 * b;
            float mu = mu2a[rr], rs = rs2a[rr];
#pragma unroll
            for (int nt = 0; nt < 8; ++nt) {
                int p0 = wn * 64 + nt * 8 + 2 * qt;
                float o0 = fmaf((acc[mt][nt][2 * b]     - mu) * rs, suv[512 + p0],     suv[768 + p0]);
                float o1 = fmaf((acc[mt][nt][2 * b + 1] - mu) * rs, suv[512 + p0 + 1], suv[768 + p0 + 1]);
                float2 o = make_float2(o0, o1);
                *(float2*)(outp + (size_t)rr * D_PROJ + p0) = o;
            }
        }
    }
#undef LOADC
#undef STATS
#undef MMABLK
#undef LOADA
#undef COMPUTE
}

// ---------------- launch ----------------
extern "C" void kernel_launch(void* const* d_in, const int* in_sizes, int n_in,
                              void* d_out, int out_size)
{
    const float* x    = (const float*)d_in[0];
    const float* g1   = (const float*)d_in[1];
    const float* b1   = (const float*)d_in[2];
    const float* W    = (const float*)d_in[3];
    const float* bias = (const float*)d_in[4];
    const float* g2   = (const float*)d_in[5];
    const float* b2   = (const float*)d_in[6];
    float* out = (float*)d_out;

    int n_tok = in_sizes[0] / D_MODEL;          // 65536
    int grid  = n_tok / MTILE;                  // 512

    prep_kernel<<<D_PROJ, 256>>>(W, g1, b1, bias);

    cudaFuncSetAttribute(fused_kernel, cudaFuncAttributeMaxDynamicSharedMemorySize, SMEM_BYTES);
    fused_kernel<<<grid, 256, SMEM_BYTES>>>(x, g2, b2, out);
}

// round 12
// speedup vs baseline: 1.1884x; 1.0397x over previous
#include <cuda_runtime.h>
#include <cstdint>
#include <cstddef>

// ---------------- problem constants ----------------
#define D_MODEL   1024
#define D_PROJ    256
#define MTILE     128                  // rows per CTA
#define NCHUNKS   32                   // K chunks of 32 fp32 (128B per row)
#define EPS1      1e-5f

// smem map (bytes):
//   [0, 4096)      suv: u[256] v[256] g2[256] b2[256]
//   [4096, 6144)   s1p[256] s2p[256]
//   [6144, 7168)   ca[128] cb[128]
//   [8192, ...)    3 stages: A 16KB + B 32KB each
//   epilogue reuses stage0: rowacc[128][4][2] (4KB), mu2[128], rs2[128]
#define SMEM_STAGE_OFF 8192
#define A_BYTES   16384                // 128 rows x 128B
#define B_BYTES   32768                // 256 rows x 128B
#define STAGE_BYTES 49152u
#define SMEM_BYTES (SMEM_STAGE_OFF + 3 * 49152)   // 155648

// ---------------- device scratch ----------------
// g_Wp: NATURAL k order, gamma1-scaled, tf32-rna rounded [256][1024]
__device__ float g_Wp[D_PROJ * D_MODEL];
__device__ float g_u[D_PROJ];
__device__ float g_v[D_PROJ];

// ---------------- helpers ----------------
static __device__ __forceinline__ uint32_t smem_u32(const void* p) {
    uint32_t a;
    asm("{ .reg .u64 t; cvta.to.shared.u64 t, %1; cvt.u32.u64 %0, t; }" : "=r"(a) : "l"(p));
    return a;
}

// conflict-free group swizzle: sigma(r) = ((r&1)<<2) | ((r>>1)&3)
static __device__ __forceinline__ uint32_t sig(int r) {
    return (((uint32_t)r & 1u) << 2) | (((uint32_t)r >> 1) & 3u);
}

#define CP_COMMIT() asm volatile("cp.async.commit_group;" ::: "memory")
#define CP_WAIT1()  asm volatile("cp.async.wait_group 1;" ::: "memory")

static __device__ __forceinline__ uint32_t f2tf32(float f) {
    uint32_t u;
    asm("cvt.rna.tf32.f32 %0, %1;" : "=r"(u) : "f"(f));
    return u;
}

// raw fp32 bits fed to tf32 MMA (truncation round on A; B pre-rounded rna).
// k mapping: natural float4 (k=4qt..4qt+3) -> step0 uses (x,y), step1 (z,w);
// A and B use the same bijection, so the contraction is exact.
#define MMA_TF32(d, a0, a1, a2, a3, b0, b1)                                   \
    asm volatile("mma.sync.aligned.m16n8k8.row.col.f32.tf32.tf32.f32 "        \
        "{%0,%1,%2,%3}, {%4,%5,%6,%7}, {%8,%9}, {%0,%1,%2,%3};"               \
        : "+f"((d)[0]), "+f"((d)[1]), "+f"((d)[2]), "+f"((d)[3])              \
        : "r"(a0), "r"(a1), "r"(a2), "r"(a3), "r"(b0), "r"(b1))

#define LDS128F(v, addr)                                                      \
    asm volatile("ld.shared.v4.f32 {%0,%1,%2,%3}, [%4];"                      \
        : "=f"((v).x), "=f"((v).y), "=f"((v).z), "=f"((v).w) : "r"(addr))

#define LDS128U(v, addr)                                                      \
    asm volatile("ld.shared.v4.b32 {%0,%1,%2,%3}, [%4];"                      \
        : "=r"((v).x), "=r"((v).y), "=r"((v).z), "=r"((v).w) : "r"(addr))

// ---------------- prep: W' = g1.*W (tf32-rna), natural layout; u, v ----------------
__global__ void __launch_bounds__(256) prep_kernel(
    const float* __restrict__ W, const float* __restrict__ g1,
    const float* __restrict__ b1, const float* __restrict__ bias)
{
    __shared__ float ru[8], rv[8];
    int p = blockIdx.x, t = threadIdx.x;
    const float* wrow = W + (size_t)p * D_MODEL;
    float u = 0.f, v = 0.f;
#pragma unroll
    for (int i = 0; i < 4; ++i) {
        int d = t + i * 256;
        float w  = wrow[d];
        float gw = g1[d] * w;
        u += gw;
        v += b1[d] * w;
        g_Wp[(size_t)p * D_MODEL + d] = __uint_as_float(f2tf32(gw));
    }
#pragma unroll
    for (int o = 16; o > 0; o >>= 1) {
        u += __shfl_xor_sync(0xFFFFFFFFu, u, o);
        v += __shfl_xor_sync(0xFFFFFFFFu, v, o);
    }
    if ((t & 31) == 0) { ru[t >> 5] = u; rv[t >> 5] = v; }
    __syncthreads();
    if (t == 0) {
        float uu = 0.f, vv = 0.f;
#pragma unroll
        for (int i = 0; i < 8; ++i) { uu += ru[i]; vv += rv[i]; }
        g_u[p] = uu;
        g_v[p] = vv + bias[p];
    }
}

// ---------------- main fused kernel ----------------
__global__ void __launch_bounds__(256, 1) fused_kernel(
    const float* __restrict__ x,
    const float* __restrict__ g2v, const float* __restrict__ b2v,
    float* __restrict__ out)
{
    extern __shared__ char smem[];
    const uint32_t sb = smem_u32(smem);
    const int tid  = threadIdx.x;
    const int lane = tid & 31;
    const int wid  = tid >> 5;
    const int wm   = wid >> 2;          // 0..1
    const int wn   = wid & 3;           // 0..3
    const int qt   = lane & 3;
    const int qr   = lane >> 2;

    float* suv = (float*)smem;          // u, v, g2, b2
    suv[tid]       = g_u[tid];
    suv[256 + tid] = g_v[tid];
    suv[512 + tid] = g2v[tid];
    suv[768 + tid] = b2v[tid];

    const size_t row0 = (size_t)blockIdx.x * MTILE;

    // ---- loader consts: thread -> (row tp + 32i, 16B group q), natural k order ----
    const int tp = tid >> 3, q = tid & 7;
    const uint32_t ldoff = (((uint32_t)q ^ sig(tp)) << 4);   // sig invariant under +32
    const uint32_t a_dst = sb + SMEM_STAGE_OFF + (uint32_t)tp * 128 + ldoff;
    const char* a_src = (const char*)x + (row0 + (size_t)tp) * 4096 + (size_t)q * 16;
    const uint32_t b_dst = sb + SMEM_STAGE_OFF + A_BYTES + (uint32_t)tp * 128 + ldoff;
    const char* b_src = (const char*)g_Wp + (size_t)tp * 4096 + (size_t)q * 16;

    // ---- fragment bases, both halves precomputed (h enters via XOR 64) ----
    const uint32_t qoff = (((uint32_t)qt ^ sig(qr)) << 4);
    const uint32_t aRow = sb + SMEM_STAGE_OFF + (uint32_t)(wm * 64 + qr) * 128;
    const uint32_t bRow = sb + SMEM_STAGE_OFF + A_BYTES + (uint32_t)(wn * 64 + qr) * 128;
    const uint32_t aF0 = aRow + qoff;
    const uint32_t aF1 = aRow + (qoff ^ 64u);
    const uint32_t bF0 = bRow + qoff;
    const uint32_t bF1 = bRow + (qoff ^ 64u);

    // ---- LN1 stat consts ----
    const int srow = tid & 127, shh = tid >> 7;
    const uint32_t sBase = sb + SMEM_STAGE_OFF + (uint32_t)srow * 128;
    const uint32_t ssig = sig(srow);
    uint32_t sOff[4];
#pragma unroll
    for (int i = 0; i < 4; ++i)
        sOff[i] = (((uint32_t)(shh * 4 + i) ^ ssig) << 4);

    float acc[4][8][4];
#pragma unroll
    for (int a = 0; a < 4; ++a)
#pragma unroll
        for (int b = 0; b < 8; ++b)
#pragma unroll
            for (int c = 0; c < 4; ++c) acc[a][b][c] = 0.f;

    float s1 = 0.f, s2 = 0.f;

#define LOADC(KC, SOFF)                                                        \
    do {                                                                       \
        const char* _a = a_src + (size_t)(KC) * 128;                           \
        _Pragma("unroll")                                                      \
        for (int i = 0; i < 4; ++i)                                            \
            asm volatile("cp.async.cg.shared.global [%0], [%1], 16;"           \
                :: "r"(a_dst + (SOFF) + (uint32_t)i * 4096),                   \
                   "l"(_a + (size_t)i * 131072));                              \
        const char* _b = b_src + (size_t)(KC) * 128;                           \
        _Pragma("unroll")                                                      \
        for (int i = 0; i < 8; ++i)                                            \
            asm volatile("cp.async.cg.shared.global [%0], [%1], 16;"           \
                :: "r"(b_dst + (SOFF) + (uint32_t)i * 4096),                   \
                   "l"(_b + (size_t)i * 131072));                              \
    } while (0)

#define STATS(SOFF)                                                            \
    do {                                                                       \
        _Pragma("unroll")                                                      \
        for (int i = 0; i < 4; ++i) {                                          \
            float4 vv;                                                         \
            LDS128F(vv, sBase + (SOFF) + sOff[i]);                             \
            s1 += (vv.x + vv.y) + (vv.z + vv.w);                               \
            s2 += (vv.x * vv.x + vv.y * vv.y) + (vv.z * vv.z + vv.w * vv.w);   \
        }                                                                      \
    } while (0)

// 16 MMAs consuming one resident A-fragment pair against 8 B fragments
#define MMABLK(MT, BLO, BHI, BB)                                               \
    do {                                                                       \
        _Pragma("unroll")                                                      \
        for (int nt = 0; nt < 8; ++nt)                                         \
            MMA_TF32(acc[MT][nt], (BLO).x, (BHI).x, (BLO).y, (BHI).y,          \
                     (BB)[nt].x, (BB)[nt].y);                                  \
        _Pragma("unroll")                                                      \
        for (int nt = 0; nt < 8; ++nt)                                         \
            MMA_TF32(acc[MT][nt], (BLO).z, (BHI).z, (BLO).w, (BHI).w,          \
                     (BB)[nt].z, (BB)[nt].w);                                  \
    } while (0)

#define LOADA(LO, HI, ADDR)                                                    \
    do { LDS128U(LO, (ADDR)); LDS128U(HI, (ADDR) + 1024); } while (0)

// software-pipelined chunk: all B hoisted, A ping-pong prefetch
#define COMPUTE(SOFF)                                                          \
    do {                                                                       \
        uint4 bb0[8], bb1[8];                                                  \
        _Pragma("unroll")                                                      \
        for (int nt = 0; nt < 8; ++nt)                                         \
            LDS128U(bb0[nt], bF0 + (SOFF) + (uint32_t)nt * 1024);              \
        _Pragma("unroll")                                                      \
        for (int nt = 0; nt < 8; ++nt)                                         \
            LDS128U(bb1[nt], bF1 + (SOFF) + (uint32_t)nt * 1024);              \
        uint4 plo, phi, qlo, qhi;                                              \
        LOADA(plo, phi, aF0 + (SOFF));             /* h0 mt0 */                \
        LOADA(qlo, qhi, aF0 + (SOFF) + 2048);      /* h0 mt1 */                \
        MMABLK(0, plo, phi, bb0);                                              \
        LOADA(plo, phi, aF0 + (SOFF) + 4096);      /* h0 mt2 */                \
        MMABLK(1, qlo, qhi, bb0);                                              \
        LOADA(qlo, qhi, aF0 + (SOFF) + 6144);      /* h0 mt3 */                \
        MMABLK(2, plo, phi, bb0);                                              \
        LOADA(plo, phi, aF1 + (SOFF));             /* h1 mt0 */                \
        MMABLK(3, qlo, qhi, bb0);                                              \
        LOADA(qlo, qhi, aF1 + (SOFF) + 2048);      /* h1 mt1 */                \
        MMABLK(0, plo, phi, bb1);                                              \
        LOADA(plo, phi, aF1 + (SOFF) + 4096);      /* h1 mt2 */                \
        MMABLK(1, qlo, qhi, bb1);                                              \
        LOADA(qlo, qhi, aF1 + (SOFF) + 6144);      /* h1 mt3 */                \
        MMABLK(2, plo, phi, bb1);                                              \
        MMABLK(3, qlo, qhi, bb1);                                              \
    } while (0)

    // ---------------- mainloop: 3-stage pipeline, wait_group 1 ----------------
    LOADC(0, 0u); CP_COMMIT();
    LOADC(1, (uint32_t)STAGE_BYTES); CP_COMMIT();

    uint32_t soff = 0;
#pragma unroll 1
    for (int kc = 0; kc < NCHUNKS; ++kc) {
        CP_WAIT1();                     // chunk kc resident
        __syncthreads();                // stage (kc+2)%3 free for overwrite
        if (kc + 2 < NCHUNKS) {
            uint32_t so2 = (soff == 0) ? 2u * STAGE_BYTES : soff - STAGE_BYTES;
            LOADC(kc + 2, so2);
        }
        CP_COMMIT();
        COMPUTE(soff);
        STATS(soff);                    // after MMAs: latency overlaps next wait
        soff = (soff == 2u * STAGE_BYTES) ? 0u : soff + STAGE_BYTES;
    }

    // ---------------- LN1 finalize ----------------
    float* s1p = (float*)(smem + 4096);
    float* s2p = s1p + 256;
    float* ca = (float*)(smem + 6144);
    float* cb = ca + 128;
    float* rowacc = (float*)(smem + SMEM_STAGE_OFF);        // [128][4][2]
    float* mu2a = (float*)(smem + SMEM_STAGE_OFF + 4096);
    float* rs2a = mu2a + 128;

    s1p[tid] = s1; s2p[tid] = s2;
    __syncthreads();

    if (tid < 128) {
        float a = s1p[tid] + s1p[tid + 128];
        float b = s2p[tid] + s2p[tid + 128];
        float mu  = a * (1.0f / (float)D_MODEL);
        float var = fmaf(-mu, mu, b * (1.0f / (float)D_MODEL));
        float rs  = rsqrtf(var + EPS1);
        ca[tid] = rs;
        cb[tid] = -mu * rs;
    }
    rowacc[tid] = 0.f; rowacc[tid + 256] = 0.f;
    rowacc[tid + 512] = 0.f; rowacc[tid + 768] = 0.f;
    __syncthreads();

    // ---------------- h = ca*acc + cb*u + v; LN2 partial sums ----------------
#pragma unroll
    for (int mt = 0; mt < 4; ++mt) {
#pragma unroll
        for (int b = 0; b < 2; ++b) {
            int rr = wm * 64 + mt * 16 + qr + 8 * b;
            float cav = ca[rr], cbv = cb[rr];
            float t1 = 0.f, t2 = 0.f;
#pragma unroll
            for (int nt = 0; nt < 8; ++nt) {
                int p0 = wn * 64 + nt * 8 + 2 * qt;
                float h0 = fmaf(cav, acc[mt][nt][2 * b],     fmaf(cbv, suv[p0],     suv[256 + p0]));
                float h1 = fmaf(cav, acc[mt][nt][2 * b + 1], fmaf(cbv, suv[p0 + 1], suv[256 + p0 + 1]));
                acc[mt][nt][2 * b]     = h0;
                acc[mt][nt][2 * b + 1] = h1;
                t1 += h0 + h1;
                t2 += h0 * h0 + h1 * h1;
            }
            t1 += __shfl_xor_sync(0xFFFFFFFFu, t1, 1);
            t2 += __shfl_xor_sync(0xFFFFFFFFu, t2, 1);
            t1 += __shfl_xor_sync(0xFFFFFFFFu, t1, 2);
            t2 += __shfl_xor_sync(0xFFFFFFFFu, t2, 2);
            if (qt == 0) {
                rowacc[(rr * 4 + wn) * 2]     = t1;
                rowacc[(rr * 4 + wn) * 2 + 1] = t2;
            }
        }
    }
    __syncthreads();

    if (tid < 128) {
        float t1 = 0.f, t2 = 0.f;
#pragma unroll
        for (int w = 0; w < 4; ++w) {
            t1 += rowacc[(tid * 4 + w) * 2];
            t2 += rowacc[(tid * 4 + w) * 2 + 1];
        }
        float mu  = t1 * (1.0f / (float)D_PROJ);
        float var = fmaf(-mu, mu, t2 * (1.0f / (float)D_PROJ));
        mu2a[tid] = mu;
        rs2a[tid] = rsqrtf(var + EPS1);
    }
    __syncthreads();

    // ---------------- normalize + store ----------------
    float* outp = out + row0 * D_PROJ;
#pragma unroll
    for (int mt = 0; mt < 4; ++mt) {
#pragma unroll
        for (int b = 0; b < 2; ++b) {
            int rr = wm * 64 + mt * 16 + qr + 8 * b;
            float mu = mu2a[rr], rs = rs2a[rr];
#pragma unroll
            for (int nt = 0; nt < 8; ++nt) {
                int p0 = wn * 64 + nt * 8 + 2 * qt;
                float o0 = fmaf((acc[mt][nt][2 * b]     - mu) * rs, suv[512 + p0],     suv[768 + p0]);
                float o1 = fmaf((acc[mt][nt][2 * b + 1] - mu) * rs, suv[512 + p0 + 1], suv[768 + p0 + 1]);
                float2 o = make_float2(o0, o1);
                *(float2*)(outp + (size_t)rr * D_PROJ + p0) = o;
            }
        }
    }
#undef LOADC
#undef STATS
#undef MMABLK
#undef LOADA
#undef COMPUTE
}

// ---------------- launch ----------------
extern "C" void kernel_launch(void* const* d_in, const int* in_sizes, int n_in,
                              void* d_out, int out_size)
{
    const float* x    = (const float*)d_in[0];
    const float* g1   = (const float*)d_in[1];
    const float* b1   = (const float*)d_in[2];
    const float* W    = (const float*)d_in[3];
    const float* bias = (const float*)d_in[4];
    const float* g2   = (const float*)d_in[5];
    const float* b2   = (const float*)d_in[6];
    float* out = (float*)d_out;

    int n_tok = in_sizes[0] / D_MODEL;          // 65536
    int grid  = n_tok / MTILE;                  // 512

    prep_kernel<<<D_PROJ, 256>>>(W, g1, b1, bias);

    cudaFuncSetAttribute(fused_kernel, cudaFuncAttributeMaxDynamicSharedMemorySize, SMEM_BYTES);
    fused_kernel<<<grid, 256, SMEM_BYTES>>>(x, g2, b2, out);
}

// round 13
// speedup vs baseline: 1.2806x; 1.0776x over previous
#include <cuda_runtime.h>
#include <cstdint>
#include <cstddef>

// ---------------- problem constants ----------------
#define D_MODEL   1024
#define D_PROJ    256
#define MTILE     64                   // rows per CTA
#define NCHUNKS   32                   // K chunks of 32 fp32 (128B per row)
#define EPS1      1e-5f

// smem map (bytes):
//   [0, 4096)      suv: u[256] v[256] g2[256] b2[256]
//   [4096, 6144)   s1p[256] s2p[256]
//   [6144, 6656)   ca[64] cb[64]
//   [8192, ...)    2 stages: A 8KB + B 32KB each
//   epilogue reuses stage0: rowacc[64][4][2] (2KB), mu2[64], rs2[64]
#define SMEM_STAGE_OFF 8192
#define A_BYTES   8192                 // 64 rows x 128B
#define B_BYTES   32768                // 256 rows x 128B
#define STAGE_BYTES 40960u
#define SMEM_BYTES (SMEM_STAGE_OFF + 2 * 40960)   // 90112 -> 2 CTAs/SM

// ---------------- device scratch ----------------
// g_Wp: NATURAL k order, gamma1-scaled, tf32-rna rounded [256][1024]
__device__ float g_Wp[D_PROJ * D_MODEL];
__device__ float g_u[D_PROJ];
__device__ float g_v[D_PROJ];

// ---------------- helpers ----------------
static __device__ __forceinline__ uint32_t smem_u32(const void* p) {
    uint32_t a;
    asm("{ .reg .u64 t; cvta.to.shared.u64 t, %1; cvt.u32.u64 %0, t; }" : "=r"(a) : "l"(p));
    return a;
}

// conflict-free group swizzle: sigma(r) = ((r&1)<<2) | ((r>>1)&3)
static __device__ __forceinline__ uint32_t sig(int r) {
    return (((uint32_t)r & 1u) << 2) | (((uint32_t)r >> 1) & 3u);
}

#define CP_COMMIT() asm volatile("cp.async.commit_group;" ::: "memory")
#define CP_WAIT1()  asm volatile("cp.async.wait_group 1;" ::: "memory")

static __device__ __forceinline__ uint32_t f2tf32(float f) {
    uint32_t u;
    asm("cvt.rna.tf32.f32 %0, %1;" : "=r"(u) : "f"(f));
    return u;
}

// raw fp32 bits fed to tf32 MMA (truncation round on A; B pre-rounded rna).
#define MMA_TF32(d, a0, a1, a2, a3, b0, b1)                                   \
    asm volatile("mma.sync.aligned.m16n8k8.row.col.f32.tf32.tf32.f32 "        \
        "{%0,%1,%2,%3}, {%4,%5,%6,%7}, {%8,%9}, {%0,%1,%2,%3};"               \
        : "+f"((d)[0]), "+f"((d)[1]), "+f"((d)[2]), "+f"((d)[3])              \
        : "r"(a0), "r"(a1), "r"(a2), "r"(a3), "r"(b0), "r"(b1))

#define LDS128F(v, addr)                                                      \
    asm volatile("ld.shared.v4.f32 {%0,%1,%2,%3}, [%4];"                      \
        : "=f"((v).x), "=f"((v).y), "=f"((v).z), "=f"((v).w) : "r"(addr))

#define LDS128U(v, addr)                                                      \
    asm volatile("ld.shared.v4.b32 {%0,%1,%2,%3}, [%4];"                      \
        : "=r"((v).x), "=r"((v).y), "=r"((v).z), "=r"((v).w) : "r"(addr))

// ---------------- prep: W' = g1.*W (tf32-rna), natural layout; u, v ----------------
__global__ void __launch_bounds__(256) prep_kernel(
    const float* __restrict__ W, const float* __restrict__ g1,
    const float* __restrict__ b1, const float* __restrict__ bias)
{
    __shared__ float ru[8], rv[8];
    int p = blockIdx.x, t = threadIdx.x;
    const float* wrow = W + (size_t)p * D_MODEL;
    float u = 0.f, v = 0.f;
#pragma unroll
    for (int i = 0; i < 4; ++i) {
        int d = t + i * 256;
        float w  = wrow[d];
        float gw = g1[d] * w;
        u += gw;
        v += b1[d] * w;
        g_Wp[(size_t)p * D_MODEL + d] = __uint_as_float(f2tf32(gw));
    }
#pragma unroll
    for (int o = 16; o > 0; o >>= 1) {
        u += __shfl_xor_sync(0xFFFFFFFFu, u, o);
        v += __shfl_xor_sync(0xFFFFFFFFu, v, o);
    }
    if ((t & 31) == 0) { ru[t >> 5] = u; rv[t >> 5] = v; }
    __syncthreads();
    if (t == 0) {
        float uu = 0.f, vv = 0.f;
#pragma unroll
        for (int i = 0; i < 8; ++i) { uu += ru[i]; vv += rv[i]; }
        g_u[p] = uu;
        g_v[p] = vv + bias[p];
    }
}

// ---------------- main fused kernel: M=64 tile, 2 CTAs/SM ----------------
__global__ void __launch_bounds__(256, 2) fused_kernel(
    const float* __restrict__ x,
    const float* __restrict__ g2v, const float* __restrict__ b2v,
    float* __restrict__ out)
{
    extern __shared__ char smem[];
    const uint32_t sb = smem_u32(smem);
    const int tid  = threadIdx.x;
    const int lane = tid & 31;
    const int wid  = tid >> 5;
    const int wm   = wid >> 2;          // 0..1 (rows wm*32..wm*32+31)
    const int wn   = wid & 3;           // 0..3 (cols wn*64..wn*64+63)
    const int qt   = lane & 3;
    const int qr   = lane >> 2;

    float* suv = (float*)smem;          // u, v, g2, b2
    suv[tid]       = g_u[tid];
    suv[256 + tid] = g_v[tid];
    suv[512 + tid] = g2v[tid];
    suv[768 + tid] = b2v[tid];

    const size_t row0 = (size_t)blockIdx.x * MTILE;

    // ---- loader consts (natural k order, 16B groups) ----
    const int tp = tid >> 3, q = tid & 7;
    const uint32_t ldoff = (((uint32_t)q ^ sig(tp)) << 4);   // sig invariant under +32
    // A: 64 rows -> thread covers rows tp, tp+32 (2 x 16B)
    const uint32_t a_dst = sb + SMEM_STAGE_OFF + (uint32_t)tp * 128 + ldoff;
    const char* a_src = (const char*)x + (row0 + (size_t)tp) * 4096 + (size_t)q * 16;
    // B: 256 rows -> thread covers rows 32i+tp, i<8 (8 x 16B)
    const uint32_t b_dst = sb + SMEM_STAGE_OFF + A_BYTES + (uint32_t)tp * 128 + ldoff;
    const char* b_src = (const char*)g_Wp + (size_t)tp * 4096 + (size_t)q * 16;

    // ---- fragment bases, both halves precomputed (h enters via XOR 64) ----
    const uint32_t qoff = (((uint32_t)qt ^ sig(qr)) << 4);
    const uint32_t aRow = sb + SMEM_STAGE_OFF + (uint32_t)(wm * 32 + qr) * 128;
    const uint32_t bRow = sb + SMEM_STAGE_OFF + A_BYTES + (uint32_t)(wn * 64 + qr) * 128;
    const uint32_t aF0 = aRow + qoff;
    const uint32_t aF1 = aRow + (qoff ^ 64u);
    const uint32_t bF0 = bRow + qoff;
    const uint32_t bF1 = bRow + (qoff ^ 64u);

    // ---- LN1 stat consts: thread -> row tid&63, groups (tid>>6)*2 + {0,1} ----
    const int srow = tid & 63, sg = tid >> 6;
    const uint32_t sBase = sb + SMEM_STAGE_OFF + (uint32_t)srow * 128;
    const uint32_t ssig = sig(srow);
    uint32_t sOff[2];
#pragma unroll
    for (int i = 0; i < 2; ++i)
        sOff[i] = (((uint32_t)(sg * 2 + i) ^ ssig) << 4);

    float acc[2][8][4];
#pragma unroll
    for (int a = 0; a < 2; ++a)
#pragma unroll
        for (int b = 0; b < 8; ++b)
#pragma unroll
            for (int c = 0; c < 4; ++c) acc[a][b][c] = 0.f;

    float s1 = 0.f, s2 = 0.f;

#define LOADC(KC, SOFF)                                                        \
    do {                                                                       \
        const char* _a = a_src + (size_t)(KC) * 128;                           \
        asm volatile("cp.async.cg.shared.global [%0], [%1], 16;"               \
            :: "r"(a_dst + (SOFF)), "l"(_a));                                  \
        asm volatile("cp.async.cg.shared.global [%0], [%1], 16;"               \
            :: "r"(a_dst + (SOFF) + 4096u), "l"(_a + 131072));                 \
        const char* _b = b_src + (size_t)(KC) * 128;                           \
        _Pragma("unroll")                                                      \
        for (int i = 0; i < 8; ++i)                                            \
            asm volatile("cp.async.cg.shared.global [%0], [%1], 16;"           \
                :: "r"(b_dst + (SOFF) + (uint32_t)i * 4096),                   \
                   "l"(_b + (size_t)i * 131072));                              \
    } while (0)

#define STATS(SOFF)                                                            \
    do {                                                                       \
        _Pragma("unroll")                                                      \
        for (int i = 0; i < 2; ++i) {                                          \
            float4 vv;                                                         \
            LDS128F(vv, sBase + (SOFF) + sOff[i]);                             \
            s1 += (vv.x + vv.y) + (vv.z + vv.w);                               \
            s2 += (vv.x * vv.x + vv.y * vv.y) + (vv.z * vv.z + vv.w * vv.w);   \
        }                                                                      \
    } while (0)

// 16 MMAs: one resident A pair vs 8 B fragments
#define MMABLK(MT, BLO, BHI, BB)                                               \
    do {                                                                       \
        _Pragma("unroll")                                                      \
        for (int nt = 0; nt < 8; ++nt)                                         \
            MMA_TF32(acc[MT][nt], (BLO).x, (BHI).x, (BLO).y, (BHI).y,          \
                     (BB)[nt].x, (BB)[nt].y);                                  \
        _Pragma("unroll")                                                      \
        for (int nt = 0; nt < 8; ++nt)                                         \
            MMA_TF32(acc[MT][nt], (BLO).z, (BHI).z, (BLO).w, (BHI).w,          \
                     (BB)[nt].z, (BB)[nt].w);                                  \
    } while (0)

#define LOADA(LO, HI, ADDR)                                                    \
    do { LDS128U(LO, (ADDR)); LDS128U(HI, (ADDR) + 1024); } while (0)

// warp tile 32x64: per half, hoist 8 B frags + 2 A pairs ping-pong
#define COMPUTE(SOFF)                                                          \
    do {                                                                       \
        _Pragma("unroll")                                                      \
        for (int h = 0; h < 2; ++h) {                                          \
            const uint32_t _af = (h ? aF1 : aF0) + (SOFF);                     \
            const uint32_t _bf = (h ? bF1 : bF0) + (SOFF);                     \
            uint4 bb[8];                                                       \
            _Pragma("unroll")                                                  \
            for (int nt = 0; nt < 8; ++nt)                                     \
                LDS128U(bb[nt], _bf + (uint32_t)nt * 1024);                    \
            uint4 plo, phi, qlo, qhi;                                          \
            LOADA(plo, phi, _af);              /* mt0 */                       \
            LOADA(qlo, qhi, _af + 2048);       /* mt1 */                       \
            MMABLK(0, plo, phi, bb);                                           \
            MMABLK(1, qlo, qhi, bb);                                           \
        }                                                                      \
    } while (0)

    // ---------------- mainloop: 2-stage ping-pong, 2 syncs/chunk ----------------
    LOADC(0, 0u); CP_COMMIT();
    LOADC(1, STAGE_BYTES); CP_COMMIT();

    uint32_t soff = 0;
#pragma unroll 1
    for (int kc = 0; kc < NCHUNKS; ++kc) {
        CP_WAIT1();                     // chunk kc resident (newest group may be empty)
        __syncthreads();
        COMPUTE(soff);
        STATS(soff);
        __syncthreads();                // all readers of stage soff done
        if (kc + 2 < NCHUNKS) LOADC(kc + 2, soff);
        CP_COMMIT();                    // unconditional: keeps wait_group accounting exact
        soff ^= STAGE_BYTES;
    }

    // ---------------- LN1 finalize ----------------
    float* s1p = (float*)(smem + 4096);             // [256]
    float* s2p = s1p + 256;                         // [256]
    float* ca  = (float*)(smem + 6144);             // [64]
    float* cb  = ca + 64;                           // [64]
    float* rowacc = (float*)(smem + SMEM_STAGE_OFF);        // [64][4][2]
    float* mu2a = (float*)(smem + SMEM_STAGE_OFF + 2048);
    float* rs2a = mu2a + 64;

    s1p[tid] = s1; s2p[tid] = s2;
    __syncthreads();

    if (tid < 64) {
        float a = (s1p[tid] + s1p[tid + 64]) + (s1p[tid + 128] + s1p[tid + 192]);
        float b = (s2p[tid] + s2p[tid + 64]) + (s2p[tid + 128] + s2p[tid + 192]);
        float mu  = a * (1.0f / (float)D_MODEL);
        float var = fmaf(-mu, mu, b * (1.0f / (float)D_MODEL));
        float rs  = rsqrtf(var + EPS1);
        ca[tid] = rs;
        cb[tid] = -mu * rs;
    }
    rowacc[tid] = 0.f; rowacc[tid + 256] = 0.f;
    __syncthreads();

    // ---------------- h = ca*acc + cb*u + v; LN2 partial sums ----------------
#pragma unroll
    for (int mt = 0; mt < 2; ++mt) {
#pragma unroll
        for (int b = 0; b < 2; ++b) {
            int rr = wm * 32 + mt * 16 + qr + 8 * b;
            float cav = ca[rr], cbv = cb[rr];
            float t1 = 0.f, t2 = 0.f;
#pragma unroll
            for (int nt = 0; nt < 8; ++nt) {
                int p0 = wn * 64 + nt * 8 + 2 * qt;
                float h0 = fmaf(cav, acc[mt][nt][2 * b],     fmaf(cbv, suv[p0],     suv[256 + p0]));
                float h1 = fmaf(cav, acc[mt][nt][2 * b + 1], fmaf(cbv, suv[p0 + 1], suv[256 + p0 + 1]));
                acc[mt][nt][2 * b]     = h0;
                acc[mt][nt][2 * b + 1] = h1;
                t1 += h0 + h1;
                t2 += h0 * h0 + h1 * h1;
            }
            t1 += __shfl_xor_sync(0xFFFFFFFFu, t1, 1);
            t2 += __shfl_xor_sync(0xFFFFFFFFu, t2, 1);
            t1 += __shfl_xor_sync(0xFFFFFFFFu, t1, 2);
            t2 += __shfl_xor_sync(0xFFFFFFFFu, t2, 2);
            if (qt == 0) {
                rowacc[(rr * 4 + wn) * 2]     = t1;
                rowacc[(rr * 4 + wn) * 2 + 1] = t2;
            }
        }
    }
    __syncthreads();

    if (tid < 64) {
        float t1 = 0.f, t2 = 0.f;
#pragma unroll
        for (int w = 0; w < 4; ++w) {
            t1 += rowacc[(tid * 4 + w) * 2];
            t2 += rowacc[(tid * 4 + w) * 2 + 1];
        }
        float mu  = t1 * (1.0f / (float)D_PROJ);
        float var = fmaf(-mu, mu, t2 * (1.0f / (float)D_PROJ));
        mu2a[tid] = mu;
        rs2a[tid] = rsqrtf(var + EPS1);
    }
    __syncthreads();

    // ---------------- normalize + store ----------------
    float* outp = out + row0 * D_PROJ;
#pragma unroll
    for (int mt = 0; mt < 2; ++mt) {
#pragma unroll
        for (int b = 0; b < 2; ++b) {
            int rr = wm * 32 + mt * 16 + qr + 8 * b;
            float mu = mu2a[rr], rs = rs2a[rr];
#pragma unroll
            for (int nt = 0; nt < 8; ++nt) {
                int p0 = wn * 64 + nt * 8 + 2 * qt;
                float o0 = fmaf((acc[mt][nt][2 * b]     - mu) * rs, suv[512 + p0],     suv[768 + p0]);
                float o1 = fmaf((acc[mt][nt][2 * b + 1] - mu) * rs, suv[512 + p0 + 1], suv[768 + p0 + 1]);
                float2 o = make_float2(o0, o1);
                *(float2*)(outp + (size_t)rr * D_PROJ + p0) = o;
            }
        }
    }
#undef LOADC
#undef STATS
#undef MMABLK
#undef LOADA
#undef COMPUTE
}

// ---------------- launch ----------------
extern "C" void kernel_launch(void* const* d_in, const int* in_sizes, int n_in,
                              void* d_out, int out_size)
{
    const float* x    = (const float*)d_in[0];
    const float* g1   = (const float*)d_in[1];
    const float* b1   = (const float*)d_in[2];
    const float* W    = (const float*)d_in[3];
    const float* bias = (const float*)d_in[4];
    const float* g2   = (const float*)d_in[5];
    const float* b2   = (const float*)d_in[6];
    float* out = (float*)d_out;

    int n_tok = in_sizes[0] / D_MODEL;          // 65536
    int grid  = n_tok / MTILE;                  // 1024

    prep_kernel<<<D_PROJ, 256>>>(W, g1, b1, bias);

    cudaFuncSetAttribute(fused_kernel, cudaFuncAttributeMaxDynamicSharedMemorySize, SMEM_BYTES);
    fused_kernel<<<grid, 256, SMEM_BYTES>>>(x, g2, b2, out);
}

// round 14
// speedup vs baseline: 2.0592x; 1.6079x over previous
#include <cuda_runtime.h>
#include <cuda_fp16.h>
#include <cstdint>
#include <cstddef>

// ---------------- problem constants ----------------
#define D_MODEL   1024
#define D_PROJ    256
#define MTILE     64                   // rows per CTA
#define NCHUNKS   32                   // K chunks of 32 (A: 128B fp32 gmem, 64B fp16 smem)
#define EPS1      1e-5f

// smem map (bytes):
//   [0, 4096)      suv: u[256] v[256] g2[256] b2[256]
//   [4096, 5120)   s1p[256]
//   [5120, 6144)   s2p[256]
//   [6144, 6656)   ca[64] cb[64]
//   [8192, 24576)  A stages: 4 x 4KB  (64 rows x 64B fp16)
//   [24576, 90112) B stages: 4 x 16KB (256 rows x 64B fp16)
//   epilogue reuses A-stage region: rowacc[64][4][2], mu2[64], rs2[64]
#define SA_OFF    8192
#define SB_OFF    24576
#define A_STAGE   4096u
#define B_STAGE   16384u
#define SMEM_BYTES 90112               // 2 CTAs/SM

// ---------------- device scratch ----------------
// g_Wp: fp16 (rna), gamma1-scaled, natural k order [256][1024]
__device__ __half g_Wp[D_PROJ * D_MODEL];
__device__ float  g_u[D_PROJ];
__device__ float  g_v[D_PROJ];

// ---------------- helpers ----------------
static __device__ __forceinline__ uint32_t smem_u32(const void* p) {
    uint32_t a;
    asm("{ .reg .u64 t; cvta.to.shared.u64 t, %1; cvt.u32.u64 %0, t; }" : "=r"(a) : "l"(p));
    return a;
}

// conflict-free 16B-group swizzle over 64B rows: sw2(r) = (r + (r>>2)) & 3
static __device__ __forceinline__ uint32_t sw2(int r) {
    return (uint32_t)((r + (r >> 2)) & 3);
}

#define CP_COMMIT() asm volatile("cp.async.commit_group;" ::: "memory")
#define CP_WAIT2()  asm volatile("cp.async.wait_group 2;" ::: "memory")

// pack two fp32 -> fp16x2 word (lo = even-k element)
#define CVT2(w, hi, lo)                                                       \
    asm("cvt.rn.f16x2.f32 %0, %1, %2;" : "=r"(w) : "f"(hi), "f"(lo))

#define LDM4(r0, r1, r2, r3, addr)                                            \
    asm volatile("ldmatrix.sync.aligned.m8n8.x4.shared.b16 {%0,%1,%2,%3}, [%4];" \
        : "=r"(r0), "=r"(r1), "=r"(r2), "=r"(r3) : "r"(addr))

#define MMA_F16(d, a0, a1, a2, a3, b0, b1)                                    \
    asm volatile("mma.sync.aligned.m16n8k16.row.col.f32.f16.f16.f32 "         \
        "{%0,%1,%2,%3}, {%4,%5,%6,%7}, {%8,%9}, {%0,%1,%2,%3};"               \
        : "+f"((d)[0]), "+f"((d)[1]), "+f"((d)[2]), "+f"((d)[3])              \
        : "r"(a0), "r"(a1), "r"(a2), "r"(a3), "r"(b0), "r"(b1))

#define STS128(addr, c0, c1, c2, c3)                                          \
    asm volatile("st.shared.v4.b32 [%0], {%1,%2,%3,%4};"                      \
        :: "r"(addr), "r"(c0), "r"(c1), "r"(c2), "r"(c3))

// ---------------- prep: W' = g1.*W (fp16-rna), natural layout; u, v ----------------
__global__ void __launch_bounds__(256) prep_kernel(
    const float* __restrict__ W, const float* __restrict__ g1,
    const float* __restrict__ b1, const float* __restrict__ bias)
{
    __shared__ float ru[8], rv[8];
    int p = blockIdx.x, t = threadIdx.x;
    const float* wrow = W + (size_t)p * D_MODEL;
    float u = 0.f, v = 0.f;
#pragma unroll
    for (int i = 0; i < 4; ++i) {
        int d = t + i * 256;
        float w  = wrow[d];
        float gw = g1[d] * w;
        __half h = __float2half_rn(gw);
        u += __half2float(h);          // exact sum of the fp16 values actually used
        v += b1[d] * w;
        g_Wp[(size_t)p * D_MODEL + d] = h;
    }
#pragma unroll
    for (int o = 16; o > 0; o >>= 1) {
        u += __shfl_xor_sync(0xFFFFFFFFu, u, o);
        v += __shfl_xor_sync(0xFFFFFFFFu, v, o);
    }
    if ((t & 31) == 0) { ru[t >> 5] = u; rv[t >> 5] = v; }
    __syncthreads();
    if (t == 0) {
        float uu = 0.f, vv = 0.f;
#pragma unroll
        for (int i = 0; i < 8; ++i) { uu += ru[i]; vv += rv[i]; }
        g_u[p] = uu;
        g_v[p] = vv + bias[p];
    }
}

// ---------------- main fused kernel: fp16 MMA, M=64, 2 CTAs/SM ----------------
__global__ void __launch_bounds__(256, 2) fused_kernel(
    const float* __restrict__ x,
    const float* __restrict__ g2v, const float* __restrict__ b2v,
    float* __restrict__ out)
{
    extern __shared__ char smem[];
    const uint32_t sb = smem_u32(smem);
    const int tid  = threadIdx.x;
    const int lane = tid & 31;
    const int wid  = tid >> 5;
    const int wm   = wid >> 2;          // 0..1 (rows wm*32..+31)
    const int wn   = wid & 3;           // 0..3 (cols wn*64..+63)
    const int qt   = lane & 3;
    const int qr   = lane >> 2;

    float* suv = (float*)smem;          // u, v, g2, b2
    suv[tid]       = g_u[tid];
    suv[256 + tid] = g_v[tid];
    suv[512 + tid] = g2v[tid];
    suv[768 + tid] = b2v[tid];

    const size_t row0 = (size_t)blockIdx.x * MTILE;
    const uint32_t sA = sb + SA_OFF;
    const uint32_t sB = sb + SB_OFF;

    // ---- A loader (LDG fp32 -> stats -> cvt -> STS fp16) ----
    const int arow = tid >> 2, aq = tid & 3;     // row 0..63, k-quarter
    const char* a_gbase = (const char*)x + (row0 + (size_t)arow) * 4096 + (size_t)aq * 32;
    const uint32_t a_sts = sA + (uint32_t)arow * 64 + ((((uint32_t)aq) ^ sw2(arow)) << 4);

    // ---- B loader (cp.async 16B x4, fp16 natural) ----
    const int btp = tid >> 2, bq = tid & 3;      // rows 64i+btp, group bq
    const uint32_t b_dst = sB + (uint32_t)btp * 64 + ((((uint32_t)bq) ^ sw2(btp)) << 4);
    const char* b_src = (const char*)g_Wp + (size_t)btp * 2048 + (size_t)bq * 16;

    // ---- ldmatrix lane addresses (stage 0, k-step 0); step1 = XOR 32 ----
    uint32_t aAd[2];
#pragma unroll
    for (int mt = 0; mt < 2; ++mt) {
        int R = wm * 32 + mt * 16 + (lane & 7) + ((lane >> 3) & 1) * 8;
        uint32_t g = (uint32_t)((lane >> 4) & 1);
        aAd[mt] = sA + (uint32_t)R * 64 + ((g ^ sw2(R)) << 4);
    }
    uint32_t bAd[4];
#pragma unroll
    for (int o = 0; o < 4; ++o) {
        int nt = 2 * o + ((lane >> 4) & 1);
        int N  = wn * 64 + nt * 8 + (lane & 7);
        uint32_t g = (uint32_t)((lane >> 3) & 1);
        bAd[o] = sB + (uint32_t)N * 64 + ((g ^ sw2(N)) << 4);
    }

    float acc[2][8][4];
#pragma unroll
    for (int a = 0; a < 2; ++a)
#pragma unroll
        for (int b = 0; b < 8; ++b)
#pragma unroll
            for (int c = 0; c < 4; ++c) acc[a][b][c] = 0.f;

    float s1 = 0.f, s2 = 0.f;
    float4 af0, af1;                    // in-flight A chunk (8 fp32)

#define LDGA(KC)                                                               \
    do {                                                                       \
        const float4* _p = (const float4*)(a_gbase + (size_t)(KC) * 128);      \
        af0 = _p[0]; af1 = _p[1];                                              \
    } while (0)

#define STSA(SOFF)                                                             \
    do {                                                                       \
        s1 += ((af0.x + af0.y) + (af0.z + af0.w))                              \
            + ((af1.x + af1.y) + (af1.z + af1.w));                             \
        s2 += ((af0.x * af0.x + af0.y * af0.y) + (af0.z * af0.z + af0.w * af0.w)) \
            + ((af1.x * af1.x + af1.y * af1.y) + (af1.z * af1.z + af1.w * af1.w)); \
        uint32_t w0, w1, w2, w3;                                               \
        CVT2(w0, af0.y, af0.x); CVT2(w1, af0.w, af0.z);                        \
        CVT2(w2, af1.y, af1.x); CVT2(w3, af1.w, af1.z);                        \
        STS128(a_sts + (SOFF), w0, w1, w2, w3);                                \
    } while (0)

#define LOADB(KC, SOFF)                                                        \
    do {                                                                       \
        const char* _b = b_src + (size_t)(KC) * 64;                            \
        _Pragma("unroll")                                                      \
        for (int i = 0; i < 4; ++i)                                            \
            asm volatile("cp.async.cg.shared.global [%0], [%1], 16;"           \
                :: "r"(b_dst + (SOFF) + (uint32_t)i * 4096),                   \
                   "l"(_b + (size_t)i * 131072));                              \
    } while (0)

#define COMPUTE(SOFFA, SOFFB)                                                  \
    do {                                                                       \
        _Pragma("unroll")                                                      \
        for (int stk = 0; stk < 2; ++stk) {                                    \
            const uint32_t xr = (uint32_t)stk << 5;                            \
            uint32_t a0[4], a1[4];                                             \
            LDM4(a0[0], a0[1], a0[2], a0[3], (aAd[0] + (SOFFA)) ^ xr);         \
            LDM4(a1[0], a1[1], a1[2], a1[3], (aAd[1] + (SOFFA)) ^ xr);         \
            _Pragma("unroll")                                                  \
            for (int o = 0; o < 4; ++o) {                                      \
                uint32_t b0, b1, b2, b3;                                       \
                LDM4(b0, b1, b2, b3, (bAd[o] + (SOFFB)) ^ xr);                 \
                MMA_F16(acc[0][2 * o],     a0[0], a0[1], a0[2], a0[3], b0, b1);\
                MMA_F16(acc[1][2 * o],     a1[0], a1[1], a1[2], a1[3], b0, b1);\
                MMA_F16(acc[0][2 * o + 1], a0[0], a0[1], a0[2], a0[3], b2, b3);\
                MMA_F16(acc[1][2 * o + 1], a1[0], a1[1], a1[2], a1[3], b2, b3);\
            }                                                                  \
        }                                                                      \
    } while (0)

    // ---------------- prologue ----------------
    LDGA(0);
    STSA(0u);                           // chunk 0 -> A stage 0 (stats chunk 0)
    LDGA(1);                            // chunk 1 in regs
    LOADB(0, 0u);            CP_COMMIT();
    LOADB(1, B_STAGE);       CP_COMMIT();
    LOADB(2, 2 * B_STAGE);   CP_COMMIT();

    // ---------------- mainloop: 4-stage, ONE sync per chunk ----------------
#pragma unroll 1
    for (int kc = 0; kc < NCHUNKS; ++kc) {
        CP_WAIT2();                                 // B(kc) resident
        if (kc + 1 < NCHUNKS) STSA((uint32_t)((kc + 1) & 3) * A_STAGE);
        __syncthreads();                            // publish A(kc+1)?, B(kc); free stage (kc-1)
        if (kc + 3 < NCHUNKS) LOADB(kc + 3, (uint32_t)((kc + 3) & 3) * B_STAGE);
        CP_COMMIT();
        if (kc + 2 < NCHUNKS) LDGA(kc + 2);
        COMPUTE((uint32_t)(kc & 3) * A_STAGE, (uint32_t)(kc & 3) * B_STAGE);
    }

    // ---------------- LN1 finalize ----------------
    float* s1p = (float*)(smem + 4096);             // [256]
    float* s2p = (float*)(smem + 5120);             // [256]
    float* ca  = (float*)(smem + 6144);             // [64]
    float* cb  = ca + 64;                           // [64]
    float* rowacc = (float*)(smem + SA_OFF);        // [64][4][2]
    float* mu2a = (float*)(smem + SA_OFF + 2048);
    float* rs2a = mu2a + 64;

    __syncthreads();                                // mainloop smem reads done
    s1p[tid] = s1; s2p[tid] = s2;
    __syncthreads();

    if (tid < 64) {
        float a = (s1p[tid * 4] + s1p[tid * 4 + 1]) + (s1p[tid * 4 + 2] + s1p[tid * 4 + 3]);
        float b = (s2p[tid * 4] + s2p[tid * 4 + 1]) + (s2p[tid * 4 + 2] + s2p[tid * 4 + 3]);
        float mu  = a * (1.0f / (float)D_MODEL);
        float var = fmaf(-mu, mu, b * (1.0f / (float)D_MODEL));
        float rs  = rsqrtf(var + EPS1);
        ca[tid] = rs;
        cb[tid] = -mu * rs;
    }
    rowacc[tid] = 0.f; rowacc[tid + 256] = 0.f;
    __syncthreads();

    // ---------------- h = ca*acc + cb*u + v; LN2 partial sums ----------------
#pragma unroll
    for (int mt = 0; mt < 2; ++mt) {
#pragma unroll
        for (int b = 0; b < 2; ++b) {
            int rr = wm * 32 + mt * 16 + qr + 8 * b;
            float cav = ca[rr], cbv = cb[rr];
            float t1 = 0.f, t2 = 0.f;
#pragma unroll
            for (int nt = 0; nt < 8; ++nt) {
                int p0 = wn * 64 + nt * 8 + 2 * qt;
                float h0 = fmaf(cav, acc[mt][nt][2 * b],     fmaf(cbv, suv[p0],     suv[256 + p0]));
                float h1 = fmaf(cav, acc[mt][nt][2 * b + 1], fmaf(cbv, suv[p0 + 1], suv[256 + p0 + 1]));
                acc[mt][nt][2 * b]     = h0;
                acc[mt][nt][2 * b + 1] = h1;
                t1 += h0 + h1;
                t2 += h0 * h0 + h1 * h1;
            }
            t1 += __shfl_xor_sync(0xFFFFFFFFu, t1, 1);
            t2 += __shfl_xor_sync(0xFFFFFFFFu, t2, 1);
            t1 += __shfl_xor_sync(0xFFFFFFFFu, t1, 2);
            t2 += __shfl_xor_sync(0xFFFFFFFFu, t2, 2);
            if (qt == 0) {
                rowacc[(rr * 4 + wn) * 2]     = t1;
                rowacc[(rr * 4 + wn) * 2 + 1] = t2;
            }
        }
    }
    __syncthreads();

    if (tid < 64) {
        float t1 = 0.f, t2 = 0.f;
#pragma unroll
        for (int w = 0; w < 4; ++w) {
            t1 += rowacc[(tid * 4 + w) * 2];
            t2 += rowacc[(tid * 4 + w) * 2 + 1];
        }
        float mu  = t1 * (1.0f / (float)D_PROJ);
        float var = fmaf(-mu, mu, t2 * (1.0f / (float)D_PROJ));
        mu2a[tid] = mu;
        rs2a[tid] = rsqrtf(var + EPS1);
    }
    __syncthreads();

    // ---------------- normalize + store ----------------
    float* outp = out + row0 * D_PROJ;
#pragma unroll
    for (int mt = 0; mt < 2; ++mt) {
#pragma unroll
        for (int b = 0; b < 2; ++b) {
            int rr = wm * 32 + mt * 16 + qr + 8 * b;
            float mu = mu2a[rr], rs = rs2a[rr];
#pragma unroll
            for (int nt = 0; nt < 8; ++nt) {
                int p0 = wn * 64 + nt * 8 + 2 * qt;
                float o0 = fmaf((acc[mt][nt][2 * b]     - mu) * rs, suv[512 + p0],     suv[768 + p0]);
                float o1 = fmaf((acc[mt][nt][2 * b + 1] - mu) * rs, suv[512 + p0 + 1], suv[768 + p0 + 1]);
                float2 o = make_float2(o0, o1);
                *(float2*)(outp + (size_t)rr * D_PROJ + p0) = o;
            }
        }
    }
#undef LDGA
#undef STSA
#undef LOADB
#undef COMPUTE
}

// ---------------- launch ----------------
extern "C" void kernel_launch(void* const* d_in, const int* in_sizes, int n_in,
                              void* d_out, int out_size)
{
    const float* x    = (const float*)d_in[0];
    const float* g1   = (const float*)d_in[1];
    const float* b1   = (const float*)d_in[2];
    const float* W    = (const float*)d_in[3];
    const float* bias = (const float*)d_in[4];
    const float* g2   = (const float*)d_in[5];
    const float* b2   = (const float*)d_in[6];
    float* out = (float*)d_out;

    int n_tok = in_sizes[0] / D_MODEL;          // 65536
    int grid  = n_tok / MTILE;                  // 1024

    prep_kernel<<<D_PROJ, 256>>>(W, g1, b1, bias);

    cudaFuncSetAttribute(fused_kernel, cudaFuncAttributeMaxDynamicSharedMemorySize, SMEM_BYTES);
    fused_kernel<<<grid, 256, SMEM_BYTES>>>(x, g2, b2, out);
}